// round 14
// baseline (speedup 1.0000x reference)
#include <cuda_runtime.h>
#include <cstdint>

// Shapes (fixed)
#define TT  4
#define SS  1024
#define DD  768
#define FFD 3072
#define TS  4096          // TT*SS
#define EPSf 1e-5f
#define NQKV 2304         // 3*DD merged QKV output width

// ---------------- scratch (device globals; no allocs allowed) ----------------
__device__ float g_qkv[(size_t)TS*NQKV];   // merged QKV pre-BN
__device__ float g_go [TS*DD];
__device__ float g_h  [TS*DD];
__device__ float g_g1 [TS*FFD];
__device__ float g_g2 [TS*DD];
__device__ int   g_qkp[8*TT*DD];           // integer partial QK sums
__device__ int8_t g_qks[TT*DD];            // talking-heads spikes
// s8 spikes
__device__ __align__(128) int8_t g_qs  [TS*DD];
__device__ __align__(128) int8_t g_ks  [TS*DD];
__device__ __align__(128) int8_t g_vs  [TS*DD];
__device__ __align__(128) int8_t g_tmps[TS*DD];
__device__ __align__(128) int8_t g_vms [TS*DD];
__device__ __align__(128) int8_t g_fs  [TS*DD];
__device__ __align__(128) int8_t g_g1s [TS*FFD];
// s8 digit-plane weights: Wt[n][plane*K + k], msb plane first
__device__ __align__(128) int8_t g_wqkvT[(size_t)NQKV*3*DD];
__device__ __align__(128) int8_t g_woT  [(size_t)DD*3*DD];
__device__ __align__(128) int8_t g_w1T  [(size_t)FFD*3*DD];
__device__ __align__(128) int8_t g_w2T  [(size_t)DD*2*FFD];

// ---------------- PTX helpers ------------------------------------------------
__device__ __forceinline__ uint32_t smem_u32(const void* p) {
    uint32_t a;
    asm("{ .reg .u64 t; cvta.to.shared.u64 t, %1; cvt.u32.u64 %0, t; }" : "=r"(a) : "l"(p));
    return a;
}
__device__ __forceinline__ void cp16(uint32_t dst, const void* src) {
    asm volatile("cp.async.cg.shared.global [%0], [%1], 16;" :: "r"(dst), "l"(src));
}
__device__ __forceinline__ void cp_commit() {
    asm volatile("cp.async.commit_group;" ::: "memory");
}
template<int N> __device__ __forceinline__ void cp_wait() {
    asm volatile("cp.async.wait_group %0;" :: "n"(N) : "memory");
}
__device__ __forceinline__ void ldm_x4(uint32_t& r0, uint32_t& r1, uint32_t& r2, uint32_t& r3,
                                       uint32_t addr) {
    asm volatile("ldmatrix.sync.aligned.m8n8.x4.shared.b16 {%0,%1,%2,%3}, [%4];"
                 : "=r"(r0), "=r"(r1), "=r"(r2), "=r"(r3) : "r"(addr));
}
__device__ __forceinline__ void mma_s8(int* d, uint32_t a0, uint32_t a1, uint32_t a2,
                                       uint32_t a3, uint32_t b0, uint32_t b1) {
    asm volatile(
        "mma.sync.aligned.m16n8k32.row.col.s32.s8.s8.s32 "
        "{%0,%1,%2,%3}, {%4,%5,%6,%7}, {%8,%9}, {%0,%1,%2,%3};"
        : "+r"(d[0]), "+r"(d[1]), "+r"(d[2]), "+r"(d[3])
        : "r"(a0), "r"(a1), "r"(a2), "r"(a3), "r"(b0), "r"(b1));
}

// =============================================================================
// IMMA s8 GEMM: C = (A @ digit-planes of W), exact-integer fold, + bias.
// A: s8 binary spikes [4096, KA] row-major. Wt: s8 [N][NP*KA], msb plane first.
// CTA tile 128x64, warp 32x32, BK=128 s8 per chunk, 3-stage cp.async.
// ISTRIDE=144 (9 x 16B): 8 consecutive rows hit 8 distinct 16B bank-groups
// (9r mod 8 = r) -> ldmatrix conflict-free.
// =============================================================================
#define ISTRIDE 144
#define IA_TILE (128*ISTRIDE)          // 18432 B
#define IB_TILE (64*ISTRIDE)           // 9216 B
#define ISTG    (IA_TILE + IB_TILE)    // 27648 B
#define IMMA_SMEM (3*ISTG)             // 82944 B

template<int KA, int NP>
__global__ void __launch_bounds__(256, 2) k_imma_gemm(
    const int8_t* __restrict__ A, const int8_t* __restrict__ Wt,
    const float* __restrict__ bias, float* __restrict__ C, int N, double invSF)
{
    constexpr int NCA = KA / 128;
    constexpr int NC = NCA * NP;
    extern __shared__ __align__(16) char smem_i[];
    const int tid = threadIdx.x, lane = tid & 31, wid = tid >> 5;
    const int wm = wid >> 1, wn = wid & 1;
    const int rowBase = blockIdx.y * 128, colBase = blockIdx.x * 64;
    const uint32_t sb = smem_u32(smem_i);

    // A loader: 128 rows x 128B, 2 threads/row x 64B (4 cp16)
    const int lrA = tid >> 1, lcA = (tid & 1) * 64;
    const int8_t* Ag = A + (size_t)(rowBase + lrA) * KA + lcA;
    const uint32_t sdA = sb + lrA * ISTRIDE + lcA;
    // B loader: 64 rows x 128B, 4 threads/row x 32B (2 cp16)
    const int lrB = tid >> 2, lcB = (tid & 3) * 32;
    const int8_t* Bg = Wt + (size_t)(colBase + lrB) * (NP * KA) + lcB;
    const uint32_t sdB = sb + IA_TILE + lrB * ISTRIDE + lcB;

#define IPRE(c) do {                                                           \
        const uint32_t so_ = ((c) % 3) * ISTG;                                 \
        const int8_t* as_ = Ag + ((c) % NCA) * 128;                            \
        const int8_t* bs_ = Bg + (size_t)(c) * 128;                            \
        cp16(sdA + so_, as_);        cp16(sdA + so_ + 16, as_ + 16);           \
        cp16(sdA + so_ + 32, as_ + 32); cp16(sdA + so_ + 48, as_ + 48);        \
        cp16(sdB + so_, bs_);        cp16(sdB + so_ + 16, bs_ + 16);           \
        cp_commit();                                                           \
    } while (0)

    const uint32_t aBase = sb + (wm * 32 + (lane & 15)) * ISTRIDE + (lane >> 4) * 16;
    const int bn_local = (lane & 7) + ((lane >> 4) & 1) * 8;
    const uint32_t bBase = sb + IA_TILE + (wn * 32 + bn_local) * ISTRIDE + ((lane >> 3) & 1) * 16;

    int iacc [2][4][4];
    int ifold[2][4][4];
    #pragma unroll
    for (int i = 0; i < 2; i++)
        #pragma unroll
        for (int j = 0; j < 4; j++)
            #pragma unroll
            for (int r = 0; r < 4; r++) { iacc[i][j][r] = 0; ifold[i][j][r] = 0; }

    IPRE(0);
    IPRE(1);

    for (int c = 0; c < NC; c++) {
        cp_wait<1>();
        __syncthreads();
        if (c + 2 < NC) IPRE(c + 2); else cp_commit();
        const uint32_t so = (c % 3) * ISTG;
        #pragma unroll
        for (int ks = 0; ks < 4; ks++) {
            uint32_t a[2][4], b[2][4];
            #pragma unroll
            for (int mi = 0; mi < 2; mi++)
                ldm_x4(a[mi][0], a[mi][1], a[mi][2], a[mi][3],
                       aBase + so + mi * 16 * ISTRIDE + ks * 32);
            #pragma unroll
            for (int nj = 0; nj < 2; nj++)
                ldm_x4(b[nj][0], b[nj][1], b[nj][2], b[nj][3],
                       bBase + so + nj * 16 * ISTRIDE + ks * 32);
            #pragma unroll
            for (int mi = 0; mi < 2; mi++)
                #pragma unroll
                for (int ni = 0; ni < 4; ni++)
                    mma_s8(iacc[mi][ni], a[mi][0], a[mi][1], a[mi][2], a[mi][3],
                           b[ni >> 1][(ni & 1) * 2], b[ni >> 1][(ni & 1) * 2 + 1]);
        }
        if (((c + 1) % NCA) == 0) {      // plane boundary: exact integer fold
            #pragma unroll
            for (int mi = 0; mi < 2; mi++)
                #pragma unroll
                for (int ni = 0; ni < 4; ni++)
                    #pragma unroll
                    for (int r = 0; r < 4; r++) {
                        ifold[mi][ni][r] = ifold[mi][ni][r] * 256 + iacc[mi][ni][r];
                        iacc[mi][ni][r] = 0;
                    }
        }
    }
#undef IPRE

    const int row0 = rowBase + wm * 32 + (lane >> 2);
    const int col0 = colBase + wn * 32 + (lane & 3) * 2;
    #pragma unroll
    for (int mi = 0; mi < 2; mi++) {
        #pragma unroll
        for (int ni = 0; ni < 4; ni++) {
            const int r = row0 + mi * 16;
            const int cc = col0 + ni * 8;
            float b0 = 0.f, b1 = 0.f;
            if (bias) { b0 = bias[cc]; b1 = bias[cc + 1]; }
            float2 v0 = { (float)((double)ifold[mi][ni][0] * invSF) + b0,
                          (float)((double)ifold[mi][ni][1] * invSF) + b1 };
            float2 v1 = { (float)((double)ifold[mi][ni][2] * invSF) + b0,
                          (float)((double)ifold[mi][ni][3] * invSF) + b1 };
            *(float2*)(C + (size_t)r * N + cc) = v0;
            *(float2*)(C + (size_t)(r + 8) * N + cc) = v1;
        }
    }
}

// ---- weight prep (coalesced, smem-tiled transpose): w[K,N] -> Wt[N][NP*K] ---
__global__ void k_prep_w_s8_t(const float* __restrict__ w, int8_t* __restrict__ wt,
                              int K, int N, int NP, float SF)
{
    __shared__ int8_t sm[3][32][33];
    const int k0 = blockIdx.x * 32, n0 = blockIdx.y * 32;
    const int tx = threadIdx.x, ty = threadIdx.y;
    #pragma unroll
    for (int i = 0; i < 4; i++) {
        const int kl = ty + i * 8;
        float v = w[(size_t)(k0 + kl) * N + n0 + tx];
        long long wi = llrintf(v * SF);
        for (int p = 0; p < NP; p++) {
            int8_t d = (int8_t)(wi & 0xFF);
            wi = (wi - d) >> 8;
            sm[NP - 1 - p][kl][tx] = d;
        }
    }
    __syncthreads();
    #pragma unroll
    for (int i = 0; i < 4; i++) {
        const int nl = ty + i * 8;
        int8_t* base = wt + (size_t)(n0 + nl) * NP * K + k0 + tx;
        for (int q = 0; q < NP; q++)
            base[(size_t)q * K] = sm[q][tx][nl];
    }
}

// ---- merged square-weight prep: z selects {wq,wk,wv,wo}, all DDxDD, NP=3 ----
__global__ void k_prep_w_sq(const float* __restrict__ wq, const float* __restrict__ wk,
                            const float* __restrict__ wv, const float* __restrict__ wo,
                            int8_t* __restrict__ wqkvT, int8_t* __restrict__ woT, float SF)
{
    __shared__ int8_t sm[3][32][33];
    const int k0 = blockIdx.x * 32, n0 = blockIdx.y * 32, z = blockIdx.z;
    const int tx = threadIdx.x, ty = threadIdx.y;
    const float* w = (z == 0) ? wq : (z == 1) ? wk : (z == 2) ? wv : wo;
    int8_t* wt = (z == 3) ? woT : (wqkvT + (size_t)z * DD * 3 * DD);
    #pragma unroll
    for (int i = 0; i < 4; i++) {
        const int kl = ty + i * 8;
        float v = w[(size_t)(k0 + kl) * DD + n0 + tx];
        long long wi = llrintf(v * SF);
        for (int p = 0; p < 3; p++) {
            int8_t d = (int8_t)(wi & 0xFF);
            wi = (wi - d) >> 8;
            sm[2 - p][kl][tx] = d;
        }
    }
    __syncthreads();
    #pragma unroll
    for (int i = 0; i < 4; i++) {
        const int nl = ty + i * 8;
        int8_t* base = wt + (size_t)(n0 + nl) * 3 * DD + k0 + tx;
        for (int q = 0; q < 3; q++)
            base[(size_t)q * DD] = sm[q][tx][nl];
    }
}

// ------- IF on input -> s8 row-major binary spikes ---------------------------
__global__ void k_if_input(const float* __restrict__ x)
{
    int idx = blockIdx.x * 256 + threadIdx.x;   // over SS*DD
    float v = 0.f;
    #pragma unroll
    for (int t = 0; t < TT; t++) {
        v += x[(size_t)t * SS * DD + idx];
        float sp = (v >= 1.f) ? 1.f : 0.f;
        g_tmps[(size_t)t * SS * DD + idx] = (int8_t)sp;
        v *= (1.f - sp);
    }
}

// ---------------- fused BatchNorm (per-s over T,DIM) + IF --------------------
template<int MODE, int DIM, typename OBT>
__global__ void __launch_bounds__(256) k_bn_if(
    const float* __restrict__ y, int ldy, const float* __restrict__ res,
    float* __restrict__ of, OBT* __restrict__ ob)
{
    constexpr int CPT = DIM / 256;
    const int s = blockIdx.x, tid = threadIdx.x;
    float vals[TT][CPT];
    float sum = 0.f, sq = 0.f;
    #pragma unroll
    for (int c = 0; c < CPT; c++) {
        int d = tid + c * 256;
        #pragma unroll
        for (int t = 0; t < TT; t++) {
            float val = y[(size_t)(t * SS + s) * ldy + d];
            vals[t][c] = val;
            sum += val; sq += val * val;
        }
    }
    __shared__ float s1[256], s2[256];
    s1[tid] = sum; s2[tid] = sq;
    __syncthreads();
    for (int o = 128; o > 0; o >>= 1) {
        if (tid < o) { s1[tid] += s1[tid + o]; s2[tid] += s2[tid + o]; }
        __syncthreads();
    }
    const float invn = 1.f / (float)(TT * DIM);
    float mean = s1[0] * invn;
    float inv  = rsqrtf(s2[0] * invn - mean * mean + EPSf);
    #pragma unroll
    for (int c = 0; c < CPT; c++) {
        int d = tid + c * 256;
        float v = 0.f;
        #pragma unroll
        for (int t = 0; t < TT; t++) {
            size_t idx = (size_t)(t * SS + s) * DIM + d;
            float nv = (vals[t][c] - mean) * inv;
            if (MODE == 0) {
                v += nv;
                float sp = (v >= 1.f) ? 1.f : 0.f;
                ob[idx] = (OBT)sp;
                v *= (1.f - sp);
            } else if (MODE == 1) {
                float hh = res[idx] + nv;
                of[idx] = hh;
                v += hh;
                float sp = (v >= 1.f) ? 1.f : 0.f;
                ob[idx] = (OBT)sp;
                v *= (1.f - sp);
            } else {
                of[idx] = res[idx] + nv;
            }
        }
    }
}

// ---- fused QKV BN+IF: grid (SS, 3), slice picks Q/K/V -> s8 spikes ----------
__global__ void __launch_bounds__(256) k_bn_if_qkv(
    const float* __restrict__ qkv, int8_t* __restrict__ qs,
    int8_t* __restrict__ ks, int8_t* __restrict__ vs)
{
    constexpr int CPT = DD / 256;
    const int s = blockIdx.x, tid = threadIdx.x;
    const int slice = blockIdx.y;
    const float* y = qkv + slice * DD;
    int8_t* ob = (slice == 0) ? qs : (slice == 1) ? ks : vs;
    float vals[TT][CPT];
    float sum = 0.f, sq = 0.f;
    #pragma unroll
    for (int c = 0; c < CPT; c++) {
        int d = tid + c * 256;
        #pragma unroll
        for (int t = 0; t < TT; t++) {
            float val = y[(size_t)(t * SS + s) * NQKV + d];
            vals[t][c] = val;
            sum += val; sq += val * val;
        }
    }
    __shared__ float s1[256], s2[256];
    s1[tid] = sum; s2[tid] = sq;
    __syncthreads();
    for (int o = 128; o > 0; o >>= 1) {
        if (tid < o) { s1[tid] += s1[tid + o]; s2[tid] += s2[tid + o]; }
        __syncthreads();
    }
    const float invn = 1.f / (float)(TT * DD);
    float mean = s1[0] * invn;
    float inv  = rsqrtf(s2[0] * invn - mean * mean + EPSf);
    #pragma unroll
    for (int c = 0; c < CPT; c++) {
        int d = tid + c * 256;
        float v = 0.f;
        #pragma unroll
        for (int t = 0; t < TT; t++) {
            size_t idx = (size_t)(t * SS + s) * DD + d;
            float nv = (vals[t][c] - mean) * inv;
            v += nv;
            float sp = (v >= 1.f) ? 1.f : 0.f;
            ob[idx] = (int8_t)sp;
            v *= (1.f - sp);
        }
    }
}

// ---------------- QK column-sum (exact integers) + IF over T -----------------
__global__ void k_qk_partial()
{
    int d = blockIdx.x * 256 + threadIdx.x;
    int t = blockIdx.z;
    int chunk = blockIdx.y;
    size_t base = (size_t)(t * SS + chunk * 128) * DD + d;
    int acc = 0;
    #pragma unroll 4
    for (int i = 0; i < 128; i++)
        acc += (int)g_qs[base + (size_t)i * DD] * (int)g_ks[base + (size_t)i * DD];
    g_qkp[(chunk * TT + t) * DD + d] = acc;
}

__global__ void k_qk_if()
{
    int d = blockIdx.x * 256 + threadIdx.x;
    int v = 0;
    #pragma unroll
    for (int t = 0; t < TT; t++) {
        int s = 0;
        #pragma unroll
        for (int c = 0; c < 8; c++) s += g_qkp[(c * TT + t) * DD + d];
        v += s;
        int sp = (v >= 1) ? 1 : 0;
        g_qks[t * DD + d] = (int8_t)sp;
        v *= (1 - sp);
    }
}

// -------- vm = V_spike & QK_spike -> s8 row-major ----------------------------
__global__ void k_vmask_s8()
{
    int idx = blockIdx.x * 256 + threadIdx.x;   // over TS*DD
    int t = idx / (SS * DD);
    int d = idx % DD;
    g_vms[idx] = (int8_t)(g_vs[idx] & g_qks[t * DD + d]);
}

// ---------------- launch ------------------------------------------------------
extern "C" void kernel_launch(void* const* d_in, const int* in_sizes, int n_in,
                              void* d_out, int out_size)
{
    const float* x  = (const float*)d_in[0];
    const float* wq = (const float*)d_in[1];
    const float* wk = (const float*)d_in[2];
    const float* wv = (const float*)d_in[3];
    const float* wo = (const float*)d_in[4];
    const float* w1 = (const float*)d_in[5];
    const float* b1 = (const float*)d_in[6];
    const float* w2 = (const float*)d_in[7];
    const float* b2 = (const float*)d_in[8];
    float* out = (float*)d_out;

    float *qkv, *go, *h, *g1, *g2;
    int8_t *qs, *ks, *vs, *tmps, *vms, *fs, *g1s, *wqkvT, *woT, *w1T, *w2T;
    cudaGetSymbolAddress((void**)&qkv, g_qkv);
    cudaGetSymbolAddress((void**)&go, g_go);     cudaGetSymbolAddress((void**)&h, g_h);
    cudaGetSymbolAddress((void**)&g1, g_g1);     cudaGetSymbolAddress((void**)&g2, g_g2);
    cudaGetSymbolAddress((void**)&qs, g_qs);     cudaGetSymbolAddress((void**)&ks, g_ks);
    cudaGetSymbolAddress((void**)&vs, g_vs);
    cudaGetSymbolAddress((void**)&tmps, g_tmps);
    cudaGetSymbolAddress((void**)&vms, g_vms);
    cudaGetSymbolAddress((void**)&fs, g_fs);     cudaGetSymbolAddress((void**)&g1s, g_g1s);
    cudaGetSymbolAddress((void**)&wqkvT, g_wqkvT);
    cudaGetSymbolAddress((void**)&woT, g_woT);
    cudaGetSymbolAddress((void**)&w1T, g_w1T);   cudaGetSymbolAddress((void**)&w2T, g_w2T);

    cudaFuncSetAttribute(k_imma_gemm<DD, 3>, cudaFuncAttributeMaxDynamicSharedMemorySize, IMMA_SMEM);
    cudaFuncSetAttribute(k_imma_gemm<FFD, 2>, cudaFuncAttributeMaxDynamicSharedMemorySize, IMMA_SMEM);

    const float  SF3  = 16777216.f;        // 2^24 (3 digit planes)
    const double IS3  = 1.0 / 16777216.0;
    const float  SF2  = 262144.f;          // 2^18 (2 digit planes)
    const double IS2  = 1.0 / 262144.0;

    const dim3 gQKV(NQKV / 64, TS / 128);   // (36, 32) = 1152 CTAs
    const dim3 gAttn(DD / 64, TS / 128);    // (12, 32)
    const dim3 gUp(FFD / 64, TS / 128);     // (48, 32)
    const dim3 gDn(DD / 64, TS / 128);      // (12, 32)
    const dim3 bP(32, 8);

    // 0) weight prep: merged square weights + FFN weights
    k_prep_w_sq<<<dim3(DD / 32, DD / 32, 4), bP>>>(wq, wk, wv, wo, wqkvT, woT, SF3);
    k_prep_w_s8_t<<<dim3(DD / 32, FFD / 32), bP>>>(w1, w1T, DD, FFD, 3, SF3);
    k_prep_w_s8_t<<<dim3(FFD / 32, DD / 32), bP>>>(w2, w2T, FFD, DD, 2, SF2);

    // 1) tmp = IF(x) -> s8 row-major spikes
    k_if_input<<<SS * DD / 256, 256>>>(x);
    // 2) merged QKV pre-BN GEMM (exact-integer IMMA)
    k_imma_gemm<DD, 3><<<gQKV, 256, IMMA_SMEM>>>(tmps, wqkvT, nullptr, qkv, NQKV, IS3);
    // 3) fused BN + IF for Q/K/V -> s8 spikes
    k_bn_if_qkv<<<dim3(SS, 3), 256>>>(qkv, qs, ks, vs);
    // 4) QK integer column-sums + talking-heads IF; masked-V s8
    k_qk_partial<<<dim3(3, 8, 4), 256>>>();
    k_qk_if<<<3, 256>>>();
    k_vmask_s8<<<TS * DD / 256, 256>>>();
    // 5) attn GEMM (exact-integer IMMA)
    k_imma_gemm<DD, 3><<<gAttn, 256, IMMA_SMEM>>>(vms, woT, nullptr, go, DD, IS3);
    // 6) h = x + BN(go); f = IF(h) -> s8 spikes
    k_bn_if<1, DD, int8_t><<<SS, 256>>>(go, DD, x, h, fs);
    // 7) FFN up (exact-integer IMMA, 3 planes)
    k_imma_gemm<DD, 3><<<gUp, 256, IMMA_SMEM>>>(fs, w1T, b1, g1, FFD, IS3);
    // 8) BN + IF -> s8 spikes
    k_bn_if<0, FFD, int8_t><<<SS, 256>>>(g1, FFD, nullptr, nullptr, g1s);
    // 9) FFN down (exact-integer IMMA, 2 planes)
    k_imma_gemm<FFD, 2><<<gDn, 256, IMMA_SMEM>>>(g1s, w2T, b2, g2, DD, IS2);
    // 10) out = h + BN(g2)
    k_bn_if<2, DD, float><<<SS, 256>>>(g2, DD, h, out, nullptr);
}

// round 15
// speedup vs baseline: 1.0307x; 1.0307x over previous
#include <cuda_runtime.h>
#include <cstdint>

// Shapes (fixed)
#define TT  4
#define SS  1024
#define DD  768
#define FFD 3072
#define TS  4096          // TT*SS
#define EPSf 1e-5f
#define NQKV 2304         // 3*DD merged QKV output width

// ---------------- scratch (device globals; no allocs allowed) ----------------
__device__ float g_qkv[(size_t)TS*NQKV];   // merged QKV pre-BN
__device__ float g_go [TS*DD];
__device__ float g_h  [TS*DD];
__device__ float g_g1 [TS*FFD];
__device__ float g_g2 [TS*DD];
__device__ int   g_qkp[8*TT*DD];           // integer partial QK sums
__device__ int8_t g_qks[TT*DD];            // talking-heads spikes
// s8 spikes
__device__ __align__(128) int8_t g_qs  [TS*DD];
__device__ __align__(128) int8_t g_ks  [TS*DD];
__device__ __align__(128) int8_t g_vs  [TS*DD];
__device__ __align__(128) int8_t g_tmps[TS*DD];
__device__ __align__(128) int8_t g_vms [TS*DD];
__device__ __align__(128) int8_t g_fs  [TS*DD];
__device__ __align__(128) int8_t g_g1s [TS*FFD];
// s8 digit-plane weights: Wt[n][plane*K + k], msb plane first
__device__ __align__(128) int8_t g_wqkvT[(size_t)NQKV*3*DD];
__device__ __align__(128) int8_t g_woT  [(size_t)DD*3*DD];
__device__ __align__(128) int8_t g_w1T  [(size_t)FFD*3*DD];
__device__ __align__(128) int8_t g_w2T  [(size_t)DD*2*FFD];

// ---------------- PTX helpers ------------------------------------------------
__device__ __forceinline__ uint32_t smem_u32(const void* p) {
    uint32_t a;
    asm("{ .reg .u64 t; cvta.to.shared.u64 t, %1; cvt.u32.u64 %0, t; }" : "=r"(a) : "l"(p));
    return a;
}
__device__ __forceinline__ void cp16(uint32_t dst, const void* src) {
    asm volatile("cp.async.cg.shared.global [%0], [%1], 16;" :: "r"(dst), "l"(src));
}
__device__ __forceinline__ void cp_commit() {
    asm volatile("cp.async.commit_group;" ::: "memory");
}
template<int N> __device__ __forceinline__ void cp_wait() {
    asm volatile("cp.async.wait_group %0;" :: "n"(N) : "memory");
}
__device__ __forceinline__ void ldm_x4(uint32_t& r0, uint32_t& r1, uint32_t& r2, uint32_t& r3,
                                       uint32_t addr) {
    asm volatile("ldmatrix.sync.aligned.m8n8.x4.shared.b16 {%0,%1,%2,%3}, [%4];"
                 : "=r"(r0), "=r"(r1), "=r"(r2), "=r"(r3) : "r"(addr));
}
__device__ __forceinline__ void mma_s8(int* d, uint32_t a0, uint32_t a1, uint32_t a2,
                                       uint32_t a3, uint32_t b0, uint32_t b1) {
    asm volatile(
        "mma.sync.aligned.m16n8k32.row.col.s32.s8.s8.s32 "
        "{%0,%1,%2,%3}, {%4,%5,%6,%7}, {%8,%9}, {%0,%1,%2,%3};"
        : "+r"(d[0]), "+r"(d[1]), "+r"(d[2]), "+r"(d[3])
        : "r"(a0), "r"(a1), "r"(a2), "r"(a3), "r"(b0), "r"(b1));
}

// =============================================================================
// IMMA s8 GEMM: C = (A @ digit-planes of W), exact-integer fold, + bias.
// A: s8 binary spikes [4096, KA] row-major. Wt: s8 [N][NP*KA], msb plane first.
// CTA tile 128x64, warp 32x32, BK=64 s8 per chunk, 4-stage cp.async.
// (R13-measured geometry; BK=128/ISTRIDE=144 regressed in R14 — ldmatrix
//  rows 8 apart collide at 1152 B ≡ 0 mod 128 B.)
// =============================================================================
#define ISTRIDE 80
#define IA_TILE (128*ISTRIDE)          // 10240 B
#define IB_TILE (64*ISTRIDE)           // 5120 B
#define ISTG    (IA_TILE + IB_TILE)    // 15360 B
#define NSTAGE  4
#define IMMA_SMEM (NSTAGE*ISTG)        // 61440 B

template<int KA, int NP>
__global__ void __launch_bounds__(256, 2) k_imma_gemm(
    const int8_t* __restrict__ A, const int8_t* __restrict__ Wt,
    const float* __restrict__ bias, float* __restrict__ C, int N, double invSF)
{
    constexpr int NCA = KA / 64;
    constexpr int NC = NCA * NP;
    extern __shared__ __align__(16) char smem_i[];
    const int tid = threadIdx.x, lane = tid & 31, wid = tid >> 5;
    const int wm = wid >> 1, wn = wid & 1;
    const int rowBase = blockIdx.y * 128, colBase = blockIdx.x * 64;
    const uint32_t sb = smem_u32(smem_i);

    const int lrA = tid >> 1, lcA = (tid & 1) * 32;
    const int8_t* Ag = A + (size_t)(rowBase + lrA) * KA + lcA;
    const uint32_t sdA = sb + lrA * ISTRIDE + lcA;
    const int lrB = tid >> 2, lcB = (tid & 3) * 16;
    const int8_t* Bg = Wt + (size_t)(colBase + lrB) * (NP * KA) + lcB;
    const uint32_t sdB = sb + IA_TILE + lrB * ISTRIDE + lcB;

#define IPRE(c) do {                                                           \
        const uint32_t so_ = ((c) % NSTAGE) * ISTG;                            \
        const int8_t* as_ = Ag + ((c) % NCA) * 64;                             \
        const int8_t* bs_ = Bg + (size_t)(c) * 64;                             \
        cp16(sdA + so_, as_);      cp16(sdA + so_ + 16, as_ + 16);             \
        cp16(sdB + so_, bs_);                                                  \
        cp_commit();                                                           \
    } while (0)

    const uint32_t aBase = sb + (wm * 32 + (lane & 15)) * ISTRIDE + (lane >> 4) * 16;
    const int bn_local = (lane & 7) + ((lane >> 4) & 1) * 8;
    const uint32_t bBase = sb + IA_TILE + (wn * 32 + bn_local) * ISTRIDE + ((lane >> 3) & 1) * 16;

    int iacc [2][4][4];
    int ifold[2][4][4];
    #pragma unroll
    for (int i = 0; i < 2; i++)
        #pragma unroll
        for (int j = 0; j < 4; j++)
            #pragma unroll
            for (int r = 0; r < 4; r++) { iacc[i][j][r] = 0; ifold[i][j][r] = 0; }

    IPRE(0);
    IPRE(1);
    IPRE(2);

    for (int c = 0; c < NC; c++) {
        cp_wait<NSTAGE - 2>();
        __syncthreads();
        if (c + 3 < NC) IPRE(c + 3); else cp_commit();
        const uint32_t so = (c % NSTAGE) * ISTG;
        #pragma unroll
        for (int ks = 0; ks < 2; ks++) {
            uint32_t a[2][4], b[2][4];
            #pragma unroll
            for (int mi = 0; mi < 2; mi++)
                ldm_x4(a[mi][0], a[mi][1], a[mi][2], a[mi][3],
                       aBase + so + mi * 16 * ISTRIDE + ks * 32);
            #pragma unroll
            for (int nj = 0; nj < 2; nj++)
                ldm_x4(b[nj][0], b[nj][1], b[nj][2], b[nj][3],
                       bBase + so + nj * 16 * ISTRIDE + ks * 32);
            #pragma unroll
            for (int mi = 0; mi < 2; mi++)
                #pragma unroll
                for (int ni = 0; ni < 4; ni++)
                    mma_s8(iacc[mi][ni], a[mi][0], a[mi][1], a[mi][2], a[mi][3],
                           b[ni >> 1][(ni & 1) * 2], b[ni >> 1][(ni & 1) * 2 + 1]);
        }
        if (((c + 1) % NCA) == 0) {      // plane boundary: exact integer fold
            #pragma unroll
            for (int mi = 0; mi < 2; mi++)
                #pragma unroll
                for (int ni = 0; ni < 4; ni++)
                    #pragma unroll
                    for (int r = 0; r < 4; r++) {
                        ifold[mi][ni][r] = ifold[mi][ni][r] * 256 + iacc[mi][ni][r];
                        iacc[mi][ni][r] = 0;
                    }
        }
    }
#undef IPRE

    const int row0 = rowBase + wm * 32 + (lane >> 2);
    const int col0 = colBase + wn * 32 + (lane & 3) * 2;
    #pragma unroll
    for (int mi = 0; mi < 2; mi++) {
        #pragma unroll
        for (int ni = 0; ni < 4; ni++) {
            const int r = row0 + mi * 16;
            const int cc = col0 + ni * 8;
            float b0 = 0.f, b1 = 0.f;
            if (bias) { b0 = bias[cc]; b1 = bias[cc + 1]; }
            float2 v0 = { (float)((double)ifold[mi][ni][0] * invSF) + b0,
                          (float)((double)ifold[mi][ni][1] * invSF) + b1 };
            float2 v1 = { (float)((double)ifold[mi][ni][2] * invSF) + b0,
                          (float)((double)ifold[mi][ni][3] * invSF) + b1 };
            *(float2*)(C + (size_t)r * N + cc) = v0;
            *(float2*)(C + (size_t)(r + 8) * N + cc) = v1;
        }
    }
}

// ---- weight prep (coalesced, smem-tiled transpose): w[K,N] -> Wt[N][NP*K] ---
__global__ void k_prep_w_s8_t(const float* __restrict__ w, int8_t* __restrict__ wt,
                              int K, int N, int NP, float SF)
{
    __shared__ int8_t sm[3][32][33];
    const int k0 = blockIdx.x * 32, n0 = blockIdx.y * 32;
    const int tx = threadIdx.x, ty = threadIdx.y;
    #pragma unroll
    for (int i = 0; i < 4; i++) {
        const int kl = ty + i * 8;
        float v = w[(size_t)(k0 + kl) * N + n0 + tx];
        long long wi = llrintf(v * SF);
        for (int p = 0; p < NP; p++) {
            int8_t d = (int8_t)(wi & 0xFF);
            wi = (wi - d) >> 8;
            sm[NP - 1 - p][kl][tx] = d;
        }
    }
    __syncthreads();
    #pragma unroll
    for (int i = 0; i < 4; i++) {
        const int nl = ty + i * 8;
        int8_t* base = wt + (size_t)(n0 + nl) * NP * K + k0 + tx;
        for (int q = 0; q < NP; q++)
            base[(size_t)q * K] = sm[q][tx][nl];
    }
}

// ---- merged square-weight prep: z selects {wq,wk,wv,wo}, all DDxDD, NP=3 ----
__global__ void k_prep_w_sq(const float* __restrict__ wq, const float* __restrict__ wk,
                            const float* __restrict__ wv, const float* __restrict__ wo,
                            int8_t* __restrict__ wqkvT, int8_t* __restrict__ woT, float SF)
{
    __shared__ int8_t sm[3][32][33];
    const int k0 = blockIdx.x * 32, n0 = blockIdx.y * 32, z = blockIdx.z;
    const int tx = threadIdx.x, ty = threadIdx.y;
    const float* w = (z == 0) ? wq : (z == 1) ? wk : (z == 2) ? wv : wo;
    int8_t* wt = (z == 3) ? woT : (wqkvT + (size_t)z * DD * 3 * DD);
    #pragma unroll
    for (int i = 0; i < 4; i++) {
        const int kl = ty + i * 8;
        float v = w[(size_t)(k0 + kl) * DD + n0 + tx];
        long long wi = llrintf(v * SF);
        for (int p = 0; p < 3; p++) {
            int8_t d = (int8_t)(wi & 0xFF);
            wi = (wi - d) >> 8;
            sm[2 - p][kl][tx] = d;
        }
    }
    __syncthreads();
    #pragma unroll
    for (int i = 0; i < 4; i++) {
        const int nl = ty + i * 8;
        int8_t* base = wt + (size_t)(n0 + nl) * 3 * DD + k0 + tx;
        for (int q = 0; q < 3; q++)
            base[(size_t)q * DD] = sm[q][tx][nl];
    }
}

// ------- IF on input -> s8 row-major binary spikes ---------------------------
__global__ void k_if_input(const float* __restrict__ x)
{
    int idx = blockIdx.x * 256 + threadIdx.x;   // over SS*DD
    float v = 0.f;
    #pragma unroll
    for (int t = 0; t < TT; t++) {
        v += x[(size_t)t * SS * DD + idx];
        float sp = (v >= 1.f) ? 1.f : 0.f;
        g_tmps[(size_t)t * SS * DD + idx] = (int8_t)sp;
        v *= (1.f - sp);
    }
}

// ---------------- fused BatchNorm (per-s over T,DIM) + IF --------------------
template<int MODE, int DIM, typename OBT>
__global__ void __launch_bounds__(256) k_bn_if(
    const float* __restrict__ y, int ldy, const float* __restrict__ res,
    float* __restrict__ of, OBT* __restrict__ ob)
{
    constexpr int CPT = DIM / 256;
    const int s = blockIdx.x, tid = threadIdx.x;
    float vals[TT][CPT];
    float sum = 0.f, sq = 0.f;
    #pragma unroll
    for (int c = 0; c < CPT; c++) {
        int d = tid + c * 256;
        #pragma unroll
        for (int t = 0; t < TT; t++) {
            float val = y[(size_t)(t * SS + s) * ldy + d];
            vals[t][c] = val;
            sum += val; sq += val * val;
        }
    }
    __shared__ float s1[256], s2[256];
    s1[tid] = sum; s2[tid] = sq;
    __syncthreads();
    for (int o = 128; o > 0; o >>= 1) {
        if (tid < o) { s1[tid] += s1[tid + o]; s2[tid] += s2[tid + o]; }
        __syncthreads();
    }
    const float invn = 1.f / (float)(TT * DIM);
    float mean = s1[0] * invn;
    float inv  = rsqrtf(s2[0] * invn - mean * mean + EPSf);
    #pragma unroll
    for (int c = 0; c < CPT; c++) {
        int d = tid + c * 256;
        float v = 0.f;
        #pragma unroll
        for (int t = 0; t < TT; t++) {
            size_t idx = (size_t)(t * SS + s) * DIM + d;
            float nv = (vals[t][c] - mean) * inv;
            if (MODE == 0) {
                v += nv;
                float sp = (v >= 1.f) ? 1.f : 0.f;
                ob[idx] = (OBT)sp;
                v *= (1.f - sp);
            } else if (MODE == 1) {
                float hh = res[idx] + nv;
                of[idx] = hh;
                v += hh;
                float sp = (v >= 1.f) ? 1.f : 0.f;
                ob[idx] = (OBT)sp;
                v *= (1.f - sp);
            } else {
                of[idx] = res[idx] + nv;
            }
        }
    }
}

// ---- fused QKV BN+IF: grid (SS, 3), slice picks Q/K/V -> s8 spikes ----------
__global__ void __launch_bounds__(256) k_bn_if_qkv(
    const float* __restrict__ qkv, int8_t* __restrict__ qs,
    int8_t* __restrict__ ks, int8_t* __restrict__ vs)
{
    constexpr int CPT = DD / 256;
    const int s = blockIdx.x, tid = threadIdx.x;
    const int slice = blockIdx.y;
    const float* y = qkv + slice * DD;
    int8_t* ob = (slice == 0) ? qs : (slice == 1) ? ks : vs;
    float vals[TT][CPT];
    float sum = 0.f, sq = 0.f;
    #pragma unroll
    for (int c = 0; c < CPT; c++) {
        int d = tid + c * 256;
        #pragma unroll
        for (int t = 0; t < TT; t++) {
            float val = y[(size_t)(t * SS + s) * NQKV + d];
            vals[t][c] = val;
            sum += val; sq += val * val;
        }
    }
    __shared__ float s1[256], s2[256];
    s1[tid] = sum; s2[tid] = sq;
    __syncthreads();
    for (int o = 128; o > 0; o >>= 1) {
        if (tid < o) { s1[tid] += s1[tid + o]; s2[tid] += s2[tid + o]; }
        __syncthreads();
    }
    const float invn = 1.f / (float)(TT * DD);
    float mean = s1[0] * invn;
    float inv  = rsqrtf(s2[0] * invn - mean * mean + EPSf);
    #pragma unroll
    for (int c = 0; c < CPT; c++) {
        int d = tid + c * 256;
        float v = 0.f;
        #pragma unroll
        for (int t = 0; t < TT; t++) {
            size_t idx = (size_t)(t * SS + s) * DD + d;
            float nv = (vals[t][c] - mean) * inv;
            v += nv;
            float sp = (v >= 1.f) ? 1.f : 0.f;
            ob[idx] = (int8_t)sp;
            v *= (1.f - sp);
        }
    }
}

// ---------------- QK column-sum (exact integers) + IF over T -----------------
__global__ void k_qk_partial()
{
    int d = blockIdx.x * 256 + threadIdx.x;
    int t = blockIdx.z;
    int chunk = blockIdx.y;
    size_t base = (size_t)(t * SS + chunk * 128) * DD + d;
    int acc = 0;
    #pragma unroll 4
    for (int i = 0; i < 128; i++)
        acc += (int)g_qs[base + (size_t)i * DD] * (int)g_ks[base + (size_t)i * DD];
    g_qkp[(chunk * TT + t) * DD + d] = acc;
}

__global__ void k_qk_if()
{
    int d = blockIdx.x * 256 + threadIdx.x;
    int v = 0;
    #pragma unroll
    for (int t = 0; t < TT; t++) {
        int s = 0;
        #pragma unroll
        for (int c = 0; c < 8; c++) s += g_qkp[(c * TT + t) * DD + d];
        v += s;
        int sp = (v >= 1) ? 1 : 0;
        g_qks[t * DD + d] = (int8_t)sp;
        v *= (1 - sp);
    }
}

// -------- vm = V_spike & QK_spike -> s8 row-major ----------------------------
__global__ void k_vmask_s8()
{
    int idx = blockIdx.x * 256 + threadIdx.x;   // over TS*DD
    int t = idx / (SS * DD);
    int d = idx % DD;
    g_vms[idx] = (int8_t)(g_vs[idx] & g_qks[t * DD + d]);
}

// ---------------- launch ------------------------------------------------------
extern "C" void kernel_launch(void* const* d_in, const int* in_sizes, int n_in,
                              void* d_out, int out_size)
{
    const float* x  = (const float*)d_in[0];
    const float* wq = (const float*)d_in[1];
    const float* wk = (const float*)d_in[2];
    const float* wv = (const float*)d_in[3];
    const float* wo = (const float*)d_in[4];
    const float* w1 = (const float*)d_in[5];
    const float* b1 = (const float*)d_in[6];
    const float* w2 = (const float*)d_in[7];
    const float* b2 = (const float*)d_in[8];
    float* out = (float*)d_out;

    float *qkv, *go, *h, *g1, *g2;
    int8_t *qs, *ks, *vs, *tmps, *vms, *fs, *g1s, *wqkvT, *woT, *w1T, *w2T;
    cudaGetSymbolAddress((void**)&qkv, g_qkv);
    cudaGetSymbolAddress((void**)&go, g_go);     cudaGetSymbolAddress((void**)&h, g_h);
    cudaGetSymbolAddress((void**)&g1, g_g1);     cudaGetSymbolAddress((void**)&g2, g_g2);
    cudaGetSymbolAddress((void**)&qs, g_qs);     cudaGetSymbolAddress((void**)&ks, g_ks);
    cudaGetSymbolAddress((void**)&vs, g_vs);
    cudaGetSymbolAddress((void**)&tmps, g_tmps);
    cudaGetSymbolAddress((void**)&vms, g_vms);
    cudaGetSymbolAddress((void**)&fs, g_fs);     cudaGetSymbolAddress((void**)&g1s, g_g1s);
    cudaGetSymbolAddress((void**)&wqkvT, g_wqkvT);
    cudaGetSymbolAddress((void**)&woT, g_woT);
    cudaGetSymbolAddress((void**)&w1T, g_w1T);   cudaGetSymbolAddress((void**)&w2T, g_w2T);

    cudaFuncSetAttribute(k_imma_gemm<DD, 3>, cudaFuncAttributeMaxDynamicSharedMemorySize, IMMA_SMEM);
    cudaFuncSetAttribute(k_imma_gemm<FFD, 2>, cudaFuncAttributeMaxDynamicSharedMemorySize, IMMA_SMEM);

    const float  SF3  = 16777216.f;        // 2^24 (3 digit planes)
    const double IS3  = 1.0 / 16777216.0;
    const float  SF2  = 262144.f;          // 2^18 (2 digit planes)
    const double IS2  = 1.0 / 262144.0;

    const dim3 gQKV(NQKV / 64, TS / 128);   // (36, 32) = 1152 CTAs
    const dim3 gAttn(DD / 64, TS / 128);    // (12, 32)
    const dim3 gUp(FFD / 64, TS / 128);     // (48, 32)
    const dim3 gDn(DD / 64, TS / 128);      // (12, 32)
    const dim3 bP(32, 8);

    // 0) weight prep: merged square weights + FFN weights
    k_prep_w_sq<<<dim3(DD / 32, DD / 32, 4), bP>>>(wq, wk, wv, wo, wqkvT, woT, SF3);
    k_prep_w_s8_t<<<dim3(DD / 32, FFD / 32), bP>>>(w1, w1T, DD, FFD, 3, SF3);
    k_prep_w_s8_t<<<dim3(FFD / 32, DD / 32), bP>>>(w2, w2T, FFD, DD, 2, SF2);

    // 1) tmp = IF(x) -> s8 row-major spikes
    k_if_input<<<SS * DD / 256, 256>>>(x);
    // 2) merged QKV pre-BN GEMM (exact-integer IMMA)
    k_imma_gemm<DD, 3><<<gQKV, 256, IMMA_SMEM>>>(tmps, wqkvT, nullptr, qkv, NQKV, IS3);
    // 3) fused BN + IF for Q/K/V -> s8 spikes
    k_bn_if_qkv<<<dim3(SS, 3), 256>>>(qkv, qs, ks, vs);
    // 4) QK integer column-sums + talking-heads IF; masked-V s8
    k_qk_partial<<<dim3(3, 8, 4), 256>>>();
    k_qk_if<<<3, 256>>>();
    k_vmask_s8<<<TS * DD / 256, 256>>>();
    // 5) attn GEMM (exact-integer IMMA)
    k_imma_gemm<DD, 3><<<gAttn, 256, IMMA_SMEM>>>(vms, woT, nullptr, go, DD, IS3);
    // 6) h = x + BN(go); f = IF(h) -> s8 spikes
    k_bn_if<1, DD, int8_t><<<SS, 256>>>(go, DD, x, h, fs);
    // 7) FFN up (exact-integer IMMA, 3 planes)
    k_imma_gemm<DD, 3><<<gUp, 256, IMMA_SMEM>>>(fs, w1T, b1, g1, FFD, IS3);
    // 8) BN + IF -> s8 spikes
    k_bn_if<0, FFD, int8_t><<<SS, 256>>>(g1, FFD, nullptr, nullptr, g1s);
    // 9) FFN down (exact-integer IMMA, 2 planes)
    k_imma_gemm<FFD, 2><<<gDn, 256, IMMA_SMEM>>>(g1s, w2T, b2, g2, DD, IS2);
    // 10) out = h + BN(g2)
    k_bn_if<2, DD, float><<<SS, 256>>>(g2, DD, h, out, nullptr);
}

// round 17
// speedup vs baseline: 1.0423x; 1.0112x over previous
#include <cuda_runtime.h>
#include <cstdint>

// Shapes (fixed)
#define TT  4
#define SS  1024
#define DD  768
#define FFD 3072
#define TS  4096          // TT*SS
#define EPSf 1e-5f
#define NQK 1536          // Q|K merged output width

// ---------------- scratch (device globals; no allocs allowed) ----------------
__device__ float g_qk_out[(size_t)TS*NQK]; // merged Q|K pre-BN
__device__ float g_v_out [(size_t)TS*DD];  // V pre-BN
__device__ float g_go [TS*DD];
__device__ float g_h  [TS*DD];
__device__ float g_g1 [TS*FFD];
__device__ float g_g2 [TS*DD];
__device__ int   g_qkp[8*TT*DD];           // integer partial QK sums
__device__ int8_t g_qks[TT*DD];            // talking-heads spikes
// s8 spikes
__device__ __align__(128) int8_t g_qs  [TS*DD];
__device__ __align__(128) int8_t g_ks  [TS*DD];
__device__ __align__(128) int8_t g_vs  [TS*DD];
__device__ __align__(128) int8_t g_tmps[TS*DD];
__device__ __align__(128) int8_t g_vms [TS*DD];
__device__ __align__(128) int8_t g_fs  [TS*DD];
__device__ __align__(128) int8_t g_g1s [TS*FFD];
// s8 digit-plane weights: Wt[n][plane*K + k], msb plane first
__device__ __align__(128) int8_t g_wqkT[(size_t)NQK*2*DD];   // Q|K, 2 planes
__device__ __align__(128) int8_t g_wvT [(size_t)DD*3*DD];    // V, 3 planes
__device__ __align__(128) int8_t g_woT [(size_t)DD*3*DD];
__device__ __align__(128) int8_t g_w1T [(size_t)FFD*3*DD];
__device__ __align__(128) int8_t g_w2T [(size_t)DD*2*FFD];

// ---------------- PTX helpers ------------------------------------------------
__device__ __forceinline__ uint32_t smem_u32(const void* p) {
    uint32_t a;
    asm("{ .reg .u64 t; cvta.to.shared.u64 t, %1; cvt.u32.u64 %0, t; }" : "=r"(a) : "l"(p));
    return a;
}
__device__ __forceinline__ void cp16(uint32_t dst, const void* src) {
    asm volatile("cp.async.cg.shared.global [%0], [%1], 16;" :: "r"(dst), "l"(src));
}
__device__ __forceinline__ void cp_commit() {
    asm volatile("cp.async.commit_group;" ::: "memory");
}
template<int N> __device__ __forceinline__ void cp_wait() {
    asm volatile("cp.async.wait_group %0;" :: "n"(N) : "memory");
}
__device__ __forceinline__ void ldm_x4(uint32_t& r0, uint32_t& r1, uint32_t& r2, uint32_t& r3,
                                       uint32_t addr) {
    asm volatile("ldmatrix.sync.aligned.m8n8.x4.shared.b16 {%0,%1,%2,%3}, [%4];"
                 : "=r"(r0), "=r"(r1), "=r"(r2), "=r"(r3) : "r"(addr));
}
__device__ __forceinline__ void mma_s8(int* d, uint32_t a0, uint32_t a1, uint32_t a2,
                                       uint32_t a3, uint32_t b0, uint32_t b1) {
    asm volatile(
        "mma.sync.aligned.m16n8k32.row.col.s32.s8.s8.s32 "
        "{%0,%1,%2,%3}, {%4,%5,%6,%7}, {%8,%9}, {%0,%1,%2,%3};"
        : "+r"(d[0]), "+r"(d[1]), "+r"(d[2]), "+r"(d[3])
        : "r"(a0), "r"(a1), "r"(a2), "r"(a3), "r"(b0), "r"(b1));
}

// =============================================================================
// IMMA s8 GEMM: C = (A @ digit-planes of W), exact-integer fold, + bias.
// A: s8 binary spikes [4096, KA] row-major. Wt: s8 [N][NP*KA], msb plane first.
// CTA tile 128x64, warp 32x32, BK=64 s8 per chunk, 4-stage cp.async.
// =============================================================================
#define ISTRIDE 80
#define IA_TILE (128*ISTRIDE)          // 10240 B
#define IB_TILE (64*ISTRIDE)           // 5120 B
#define ISTG    (IA_TILE + IB_TILE)    // 15360 B
#define NSTAGE  4
#define IMMA_SMEM (NSTAGE*ISTG)        // 61440 B

template<int KA, int NP>
__global__ void __launch_bounds__(256, 2) k_imma_gemm(
    const int8_t* __restrict__ A, const int8_t* __restrict__ Wt,
    const float* __restrict__ bias, float* __restrict__ C, int N, double invSF)
{
    constexpr int NCA = KA / 64;
    constexpr int NC = NCA * NP;
    extern __shared__ __align__(16) char smem_i[];
    const int tid = threadIdx.x, lane = tid & 31, wid = tid >> 5;
    const int wm = wid >> 1, wn = wid & 1;
    const int rowBase = blockIdx.y * 128, colBase = blockIdx.x * 64;
    const uint32_t sb = smem_u32(smem_i);

    const int lrA = tid >> 1, lcA = (tid & 1) * 32;
    const int8_t* Ag = A + (size_t)(rowBase + lrA) * KA + lcA;
    const uint32_t sdA = sb + lrA * ISTRIDE + lcA;
    const int lrB = tid >> 2, lcB = (tid & 3) * 16;
    const int8_t* Bg = Wt + (size_t)(colBase + lrB) * (NP * KA) + lcB;
    const uint32_t sdB = sb + IA_TILE + lrB * ISTRIDE + lcB;

#define IPRE(c) do {                                                           \
        const uint32_t so_ = ((c) % NSTAGE) * ISTG;                            \
        const int8_t* as_ = Ag + ((c) % NCA) * 64;                             \
        const int8_t* bs_ = Bg + (size_t)(c) * 64;                             \
        cp16(sdA + so_, as_);      cp16(sdA + so_ + 16, as_ + 16);             \
        cp16(sdB + so_, bs_);                                                  \
        cp_commit();                                                           \
    } while (0)

    const uint32_t aBase = sb + (wm * 32 + (lane & 15)) * ISTRIDE + (lane >> 4) * 16;
    const int bn_local = (lane & 7) + ((lane >> 4) & 1) * 8;
    const uint32_t bBase = sb + IA_TILE + (wn * 32 + bn_local) * ISTRIDE + ((lane >> 3) & 1) * 16;

    int iacc [2][4][4];
    int ifold[2][4][4];
    #pragma unroll
    for (int i = 0; i < 2; i++)
        #pragma unroll
        for (int j = 0; j < 4; j++)
            #pragma unroll
            for (int r = 0; r < 4; r++) { iacc[i][j][r] = 0; ifold[i][j][r] = 0; }

    IPRE(0);
    IPRE(1);
    IPRE(2);

    for (int c = 0; c < NC; c++) {
        cp_wait<NSTAGE - 2>();
        __syncthreads();
        if (c + 3 < NC) IPRE(c + 3); else cp_commit();
        const uint32_t so = (c % NSTAGE) * ISTG;
        #pragma unroll
        for (int ks = 0; ks < 2; ks++) {
            uint32_t a[2][4], b[2][4];
            #pragma unroll
            for (int mi = 0; mi < 2; mi++)
                ldm_x4(a[mi][0], a[mi][1], a[mi][2], a[mi][3],
                       aBase + so + mi * 16 * ISTRIDE + ks * 32);
            #pragma unroll
            for (int nj = 0; nj < 2; nj++)
                ldm_x4(b[nj][0], b[nj][1], b[nj][2], b[nj][3],
                       bBase + so + nj * 16 * ISTRIDE + ks * 32);
            #pragma unroll
            for (int mi = 0; mi < 2; mi++)
                #pragma unroll
                for (int ni = 0; ni < 4; ni++)
                    mma_s8(iacc[mi][ni], a[mi][0], a[mi][1], a[mi][2], a[mi][3],
                           b[ni >> 1][(ni & 1) * 2], b[ni >> 1][(ni & 1) * 2 + 1]);
        }
        if (((c + 1) % NCA) == 0) {      // plane boundary: exact integer fold
            #pragma unroll
            for (int mi = 0; mi < 2; mi++)
                #pragma unroll
                for (int ni = 0; ni < 4; ni++)
                    #pragma unroll
                    for (int r = 0; r < 4; r++) {
                        ifold[mi][ni][r] = ifold[mi][ni][r] * 256 + iacc[mi][ni][r];
                        iacc[mi][ni][r] = 0;
                    }
        }
    }
#undef IPRE

    const int row0 = rowBase + wm * 32 + (lane >> 2);
    const int col0 = colBase + wn * 32 + (lane & 3) * 2;
    #pragma unroll
    for (int mi = 0; mi < 2; mi++) {
        #pragma unroll
        for (int ni = 0; ni < 4; ni++) {
            const int r = row0 + mi * 16;
            const int cc = col0 + ni * 8;
            float b0 = 0.f, b1 = 0.f;
            if (bias) { b0 = bias[cc]; b1 = bias[cc + 1]; }
            float2 v0 = { (float)((double)ifold[mi][ni][0] * invSF) + b0,
                          (float)((double)ifold[mi][ni][1] * invSF) + b1 };
            float2 v1 = { (float)((double)ifold[mi][ni][2] * invSF) + b0,
                          (float)((double)ifold[mi][ni][3] * invSF) + b1 };
            *(float2*)(C + (size_t)r * N + cc) = v0;
            *(float2*)(C + (size_t)(r + 8) * N + cc) = v1;
        }
    }
}

// ---- weight prep (coalesced, smem-tiled transpose): w[K,N] -> Wt[N][NP*K] ---
__global__ void k_prep_w_s8_t(const float* __restrict__ w, int8_t* __restrict__ wt,
                              int K, int N, int NP, float SF)
{
    __shared__ int8_t sm[3][32][33];
    const int k0 = blockIdx.x * 32, n0 = blockIdx.y * 32;
    const int tx = threadIdx.x, ty = threadIdx.y;
    #pragma unroll
    for (int i = 0; i < 4; i++) {
        const int kl = ty + i * 8;
        float v = w[(size_t)(k0 + kl) * N + n0 + tx];
        long long wi = llrintf(v * SF);
        for (int p = 0; p < NP; p++) {
            int8_t d = (int8_t)(wi & 0xFF);
            wi = (wi - d) >> 8;
            sm[NP - 1 - p][kl][tx] = d;
        }
    }
    __syncthreads();
    #pragma unroll
    for (int i = 0; i < 4; i++) {
        const int nl = ty + i * 8;
        int8_t* base = wt + (size_t)(n0 + nl) * NP * K + k0 + tx;
        for (int q = 0; q < NP; q++)
            base[(size_t)q * K] = sm[q][tx][nl];
    }
}

// ---- merged square-weight prep: z selects {wq(2pl), wk(2pl), wv(3pl), wo(3pl)}
__global__ void k_prep_w_sq(const float* __restrict__ wq, const float* __restrict__ wk,
                            const float* __restrict__ wv, const float* __restrict__ wo,
                            int8_t* __restrict__ wqkT, int8_t* __restrict__ wvT,
                            int8_t* __restrict__ woT, float SF2p, float SF3p)
{
    __shared__ int8_t sm[3][32][33];
    const int k0 = blockIdx.x * 32, n0 = blockIdx.y * 32, z = blockIdx.z;
    const int tx = threadIdx.x, ty = threadIdx.y;
    const float* w = (z == 0) ? wq : (z == 1) ? wk : (z == 2) ? wv : wo;
    const int NP = (z < 2) ? 2 : 3;
    const float SF = (z < 2) ? SF2p : SF3p;
    int8_t* wt = (z == 0) ? wqkT
               : (z == 1) ? (wqkT + (size_t)DD * 2 * DD)
               : (z == 2) ? wvT : woT;
    #pragma unroll
    for (int i = 0; i < 4; i++) {
        const int kl = ty + i * 8;
        float v = w[(size_t)(k0 + kl) * DD + n0 + tx];
        long long wi = llrintf(v * SF);
        for (int p = 0; p < NP; p++) {
            int8_t d = (int8_t)(wi & 0xFF);
            wi = (wi - d) >> 8;
            sm[NP - 1 - p][kl][tx] = d;
        }
    }
    __syncthreads();
    #pragma unroll
    for (int i = 0; i < 4; i++) {
        const int nl = ty + i * 8;
        int8_t* base = wt + (size_t)(n0 + nl) * NP * DD + k0 + tx;
        for (int q = 0; q < NP; q++)
            base[(size_t)q * DD] = sm[q][tx][nl];
    }
}

// ------- IF on input -> s8 row-major binary spikes ---------------------------
__global__ void k_if_input(const float* __restrict__ x)
{
    int idx = blockIdx.x * 256 + threadIdx.x;   // over SS*DD
    float v = 0.f;
    #pragma unroll
    for (int t = 0; t < TT; t++) {
        v += x[(size_t)t * SS * DD + idx];
        float sp = (v >= 1.f) ? 1.f : 0.f;
        g_tmps[(size_t)t * SS * DD + idx] = (int8_t)sp;
        v *= (1.f - sp);
    }
}

// ---------------- fused BatchNorm (per-s over T,DIM) + IF --------------------
template<int MODE, int DIM, typename OBT>
__global__ void __launch_bounds__(256) k_bn_if(
    const float* __restrict__ y, int ldy, const float* __restrict__ res,
    float* __restrict__ of, OBT* __restrict__ ob)
{
    constexpr int CPT = DIM / 256;
    const int s = blockIdx.x, tid = threadIdx.x;
    float vals[TT][CPT];
    float sum = 0.f, sq = 0.f;
    #pragma unroll
    for (int c = 0; c < CPT; c++) {
        int d = tid + c * 256;
        #pragma unroll
        for (int t = 0; t < TT; t++) {
            float val = y[(size_t)(t * SS + s) * ldy + d];
            vals[t][c] = val;
            sum += val; sq += val * val;
        }
    }
    __shared__ float s1[256], s2[256];
    s1[tid] = sum; s2[tid] = sq;
    __syncthreads();
    for (int o = 128; o > 0; o >>= 1) {
        if (tid < o) { s1[tid] += s1[tid + o]; s2[tid] += s2[tid + o]; }
        __syncthreads();
    }
    const float invn = 1.f / (float)(TT * DIM);
    float mean = s1[0] * invn;
    float inv  = rsqrtf(s2[0] * invn - mean * mean + EPSf);
    #pragma unroll
    for (int c = 0; c < CPT; c++) {
        int d = tid + c * 256;
        float v = 0.f;
        #pragma unroll
        for (int t = 0; t < TT; t++) {
            size_t idx = (size_t)(t * SS + s) * DIM + d;
            float nv = (vals[t][c] - mean) * inv;
            if (MODE == 0) {
                v += nv;
                float sp = (v >= 1.f) ? 1.f : 0.f;
                ob[idx] = (OBT)sp;
                v *= (1.f - sp);
            } else if (MODE == 1) {
                float hh = res[idx] + nv;
                of[idx] = hh;
                v += hh;
                float sp = (v >= 1.f) ? 1.f : 0.f;
                ob[idx] = (OBT)sp;
                v *= (1.f - sp);
            } else {
                of[idx] = res[idx] + nv;
            }
        }
    }
}

// ---- fused QKV BN+IF: grid (SS, 3); slices 0,1 read qk_out, 2 reads v_out ---
__global__ void __launch_bounds__(256) k_bn_if_qkv(
    const float* __restrict__ qk_out, const float* __restrict__ v_out,
    int8_t* __restrict__ qs, int8_t* __restrict__ ks, int8_t* __restrict__ vs)
{
    constexpr int CPT = DD / 256;
    const int s = blockIdx.x, tid = threadIdx.x;
    const int slice = blockIdx.y;
    const float* y = (slice == 2) ? v_out : (qk_out + slice * DD);
    const int ldy = (slice == 2) ? DD : NQK;
    int8_t* ob = (slice == 0) ? qs : (slice == 1) ? ks : vs;
    float vals[TT][CPT];
    float sum = 0.f, sq = 0.f;
    #pragma unroll
    for (int c = 0; c < CPT; c++) {
        int d = tid + c * 256;
        #pragma unroll
        for (int t = 0; t < TT; t++) {
            float val = y[(size_t)(t * SS + s) * ldy + d];
            vals[t][c] = val;
            sum += val; sq += val * val;
        }
    }
    __shared__ float s1[256], s2[256];
    s1[tid] = sum; s2[tid] = sq;
    __syncthreads();
    for (int o = 128; o > 0; o >>= 1) {
        if (tid < o) { s1[tid] += s1[tid + o]; s2[tid] += s2[tid + o]; }
        __syncthreads();
    }
    const float invn = 1.f / (float)(TT * DD);
    float mean = s1[0] * invn;
    float inv  = rsqrtf(s2[0] * invn - mean * mean + EPSf);
    #pragma unroll
    for (int c = 0; c < CPT; c++) {
        int d = tid + c * 256;
        float v = 0.f;
        #pragma unroll
        for (int t = 0; t < TT; t++) {
            size_t idx = (size_t)(t * SS + s) * DD + d;
            float nv = (vals[t][c] - mean) * inv;
            v += nv;
            float sp = (v >= 1.f) ? 1.f : 0.f;
            ob[idx] = (int8_t)sp;
            v *= (1.f - sp);
        }
    }
}

// ---------------- QK column-sum (exact integers) + IF over T -----------------
__global__ void k_qk_partial()
{
    int d = blockIdx.x * 256 + threadIdx.x;
    int t = blockIdx.z;
    int chunk = blockIdx.y;
    size_t base = (size_t)(t * SS + chunk * 128) * DD + d;
    int acc = 0;
    #pragma unroll 4
    for (int i = 0; i < 128; i++)
        acc += (int)g_qs[base + (size_t)i * DD] * (int)g_ks[base + (size_t)i * DD];
    g_qkp[(chunk * TT + t) * DD + d] = acc;
}

__global__ void k_qk_if()
{
    int d = blockIdx.x * 256 + threadIdx.x;
    int v = 0;
    #pragma unroll
    for (int t = 0; t < TT; t++) {
        int s = 0;
        #pragma unroll
        for (int c = 0; c < 8; c++) s += g_qkp[(c * TT + t) * DD + d];
        v += s;
        int sp = (v >= 1) ? 1 : 0;
        g_qks[t * DD + d] = (int8_t)sp;
        v *= (1 - sp);
    }
}

// -------- vm = V_spike & QK_spike -> s8 row-major ----------------------------
__global__ void k_vmask_s8()
{
    int idx = blockIdx.x * 256 + threadIdx.x;   // over TS*DD
    int t = idx / (SS * DD);
    int d = idx % DD;
    g_vms[idx] = (int8_t)(g_vs[idx] & g_qks[t * DD + d]);
}

// ---------------- launch ------------------------------------------------------
extern "C" void kernel_launch(void* const* d_in, const int* in_sizes, int n_in,
                              void* d_out, int out_size)
{
    const float* x  = (const float*)d_in[0];
    const float* wq = (const float*)d_in[1];
    const float* wk = (const float*)d_in[2];
    const float* wv = (const float*)d_in[3];
    const float* wo = (const float*)d_in[4];
    const float* w1 = (const float*)d_in[5];
    const float* b1 = (const float*)d_in[6];
    const float* w2 = (const float*)d_in[7];
    const float* b2 = (const float*)d_in[8];
    float* out = (float*)d_out;

    float *qk_out, *v_out, *go, *h, *g1, *g2;
    int8_t *qs, *ks, *vs, *tmps, *vms, *fs, *g1s, *wqkT, *wvT, *woT, *w1T, *w2T;
    cudaGetSymbolAddress((void**)&qk_out, g_qk_out);
    cudaGetSymbolAddress((void**)&v_out, g_v_out);
    cudaGetSymbolAddress((void**)&go, g_go);     cudaGetSymbolAddress((void**)&h, g_h);
    cudaGetSymbolAddress((void**)&g1, g_g1);     cudaGetSymbolAddress((void**)&g2, g_g2);
    cudaGetSymbolAddress((void**)&qs, g_qs);     cudaGetSymbolAddress((void**)&ks, g_ks);
    cudaGetSymbolAddress((void**)&vs, g_vs);
    cudaGetSymbolAddress((void**)&tmps, g_tmps);
    cudaGetSymbolAddress((void**)&vms, g_vms);
    cudaGetSymbolAddress((void**)&fs, g_fs);     cudaGetSymbolAddress((void**)&g1s, g_g1s);
    cudaGetSymbolAddress((void**)&wqkT, g_wqkT);
    cudaGetSymbolAddress((void**)&wvT, g_wvT);
    cudaGetSymbolAddress((void**)&woT, g_woT);
    cudaGetSymbolAddress((void**)&w1T, g_w1T);   cudaGetSymbolAddress((void**)&w2T, g_w2T);

    cudaFuncSetAttribute(k_imma_gemm<DD, 2>, cudaFuncAttributeMaxDynamicSharedMemorySize, IMMA_SMEM);
    cudaFuncSetAttribute(k_imma_gemm<DD, 3>, cudaFuncAttributeMaxDynamicSharedMemorySize, IMMA_SMEM);
    cudaFuncSetAttribute(k_imma_gemm<FFD, 2>, cudaFuncAttributeMaxDynamicSharedMemorySize, IMMA_SMEM);

    const float  SF3  = 16777216.f;        // 2^24 (3 digit planes)
    const double IS3  = 1.0 / 16777216.0;
    const float  SF2w = 131072.f;          // 2^17 (2 planes, Q/K: |w|max*SF ~ 23k < 2^15)
    const double IS2w = 1.0 / 131072.0;
    const float  SF2  = 262144.f;          // 2^18 (2 planes, FFN-down)
    const double IS2  = 1.0 / 262144.0;

    const dim3 gQK(NQK / 64, TS / 128);     // (24, 32) = 768 CTAs
    const dim3 gV(DD / 64, TS / 128);       // (12, 32)
    const dim3 gAttn(DD / 64, TS / 128);    // (12, 32)
    const dim3 gUp(FFD / 64, TS / 128);     // (48, 32)
    const dim3 gDn(DD / 64, TS / 128);      // (12, 32)
    const dim3 bP(32, 8);

    // 0) weight prep: merged square weights (Q/K 2-plane@2^17, V/O 3-plane) + FFN
    k_prep_w_sq<<<dim3(DD / 32, DD / 32, 4), bP>>>(wq, wk, wv, wo, wqkT, wvT, woT, SF2w, SF3);
    k_prep_w_s8_t<<<dim3(DD / 32, FFD / 32), bP>>>(w1, w1T, DD, FFD, 3, SF3);
    k_prep_w_s8_t<<<dim3(FFD / 32, DD / 32), bP>>>(w2, w2T, FFD, DD, 2, SF2);

    // 1) tmp = IF(x) -> s8 row-major spikes
    k_if_input<<<SS * DD / 256, 256>>>(x);
    // 2) Q|K pre-BN GEMM (2 planes: Q/K flips absorbed by integer QK margins)
    k_imma_gemm<DD, 2><<<gQK, 256, IMMA_SMEM>>>(tmps, wqkT, nullptr, qk_out, NQK, IS2w);
    //    V pre-BN GEMM (3 planes: V flips would propagate)
    k_imma_gemm<DD, 3><<<gV, 256, IMMA_SMEM>>>(tmps, wvT, nullptr, v_out, DD, IS3);
    // 3) fused BN + IF for Q/K/V -> s8 spikes
    k_bn_if_qkv<<<dim3(SS, 3), 256>>>(qk_out, v_out, qs, ks, vs);
    // 4) QK integer column-sums + talking-heads IF; masked-V s8
    k_qk_partial<<<dim3(3, 8, 4), 256>>>();
    k_qk_if<<<3, 256>>>();
    k_vmask_s8<<<TS * DD / 256, 256>>>();
    // 5) attn GEMM (exact-integer IMMA, 3 planes)
    k_imma_gemm<DD, 3><<<gAttn, 256, IMMA_SMEM>>>(vms, woT, nullptr, go, DD, IS3);
    // 6) h = x + BN(go); f = IF(h) -> s8 spikes
    k_bn_if<1, DD, int8_t><<<SS, 256>>>(go, DD, x, h, fs);
    // 7) FFN up (exact-integer IMMA, 3 planes)
    k_imma_gemm<DD, 3><<<gUp, 256, IMMA_SMEM>>>(fs, w1T, b1, g1, FFD, IS3);
    // 8) BN + IF -> s8 spikes
    k_bn_if<0, FFD, int8_t><<<SS, 256>>>(g1, FFD, nullptr, nullptr, g1s);
    // 9) FFN down (exact-integer IMMA, 2 planes)
    k_imma_gemm<FFD, 2><<<gDn, 256, IMMA_SMEM>>>(g1s, w2T, b2, g2, DD, IS2);
    // 10) out = h + BN(g2)
    k_bn_if<2, DD, float><<<SS, 256>>>(g2, DD, h, out, nullptr);
}